// round 15
// baseline (speedup 1.0000x reference)
#include <cuda_runtime.h>
#include <math.h>

#define BB 32
#define CC 256
#define HH 56
#define WW 56
#define HWSZ (HH * WW)            // 3136
#define NPIX (BB * HWSZ)          // 100352
#define NELEM (BB * CC * HWSZ)    // 25690112
#define G 8                       // channel groups
#define CPG (CC / G)              // 32 channels per group

// Batch chunking: process 16 batches at a time so each chunk of x (51.4 MB)
// stays L2-resident between its reduce (first read) and its apply (re-read).
#define BPC 16                    // batches per chunk
#define NCHUNK (BB / BPC)         // 2
#define CH_NPIX (BPC * HWSZ)      // 50176
#define CH_NPIX4 (CH_NPIX / 4)    // 12544
#define CH_NELEM4 (BPC * CC * HWSZ / 4)  // 3211264

// Scratch (device globals — no allocation allowed anywhere in this file)
__device__ __align__(16) float g_psum[G * NPIX];   // 3.2 MB
__device__ __align__(16) float g_pmax[G * NPIX];   // 3.2 MB
__device__ __align__(16) float g_avg[NPIX];
__device__ __align__(16) float g_mx[NPIX];
__device__ __align__(16) float g_att[NPIX];

// ---------------------------------------------------------------------------
// Kernel 1a: split-K channel reduction over one batch chunk.
// blockIdx.y = channel group. x read with default .ca -> chunk stays in L2
// for the apply kernel. Partials stored .cs (evict-first, read-once data).
// ---------------------------------------------------------------------------
__global__ void __launch_bounds__(256) reduce_partial_kernel(const float* __restrict__ x,
                                                             int b0) {
    int i = blockIdx.x * blockDim.x + threadIdx.x;   // pixel-quad idx in chunk
    if (i >= CH_NPIX4) return;
    int g = blockIdx.y;
    int pixl = i * 4;
    int bl = pixl / HWSZ;
    int hw = pixl - bl * HWSZ;
    int b = b0 + bl;
    const float4* p = (const float4*)(x + (size_t)b * CC * HWSZ
                                        + (size_t)(g * CPG) * HWSZ + hw);
    const int cs = HWSZ / 4;   // channel stride in float4 units (784)

    float4 s0 = make_float4(0.f, 0.f, 0.f, 0.f), s1 = s0;
    float4 m0 = make_float4(-INFINITY, -INFINITY, -INFINITY, -INFINITY), m1 = m0;

#pragma unroll
    for (int c = 0; c < CPG; c += 8) {
        float4 v[8];
#pragma unroll
        for (int j = 0; j < 8; j++)
            v[j] = __ldg(p + (size_t)(c + j) * cs);
#pragma unroll
        for (int j = 0; j < 8; j += 2) {
            s0.x += v[j].x;   s0.y += v[j].y;   s0.z += v[j].z;   s0.w += v[j].w;
            s1.x += v[j+1].x; s1.y += v[j+1].y; s1.z += v[j+1].z; s1.w += v[j+1].w;
            m0.x = fmaxf(m0.x, v[j].x);   m0.y = fmaxf(m0.y, v[j].y);
            m0.z = fmaxf(m0.z, v[j].z);   m0.w = fmaxf(m0.w, v[j].w);
            m1.x = fmaxf(m1.x, v[j+1].x); m1.y = fmaxf(m1.y, v[j+1].y);
            m1.z = fmaxf(m1.z, v[j+1].z); m1.w = fmaxf(m1.w, v[j+1].w);
        }
    }
    float4 s, m;
    s.x = s0.x + s1.x; s.y = s0.y + s1.y; s.z = s0.z + s1.z; s.w = s0.w + s1.w;
    m.x = fmaxf(m0.x, m1.x); m.y = fmaxf(m0.y, m1.y);
    m.z = fmaxf(m0.z, m1.z); m.w = fmaxf(m0.w, m1.w);
    size_t gp = (size_t)g * NPIX + (size_t)b * HWSZ + hw;
    __stcs((float4*)(g_psum + gp), s);
    __stcs((float4*)(g_pmax + gp), m);
}

// ---------------------------------------------------------------------------
// Kernel 1b: combine the 8 partials into avg/max planes for one chunk.
// Partials read .cs (dead after this).
// ---------------------------------------------------------------------------
__global__ void combine_kernel(int b0) {
    int i = blockIdx.x * blockDim.x + threadIdx.x;   // pixel-quad idx in chunk
    if (i >= CH_NPIX4) return;
    int pix = b0 * HWSZ + i * 4;                     // global pixel

    float4 s = make_float4(0.f, 0.f, 0.f, 0.f);
    float4 m = make_float4(-INFINITY, -INFINITY, -INFINITY, -INFINITY);
#pragma unroll
    for (int g = 0; g < G; g++) {
        float4 ps = __ldcs((const float4*)(g_psum + (size_t)g * NPIX + pix));
        float4 pm = __ldcs((const float4*)(g_pmax + (size_t)g * NPIX + pix));
        s.x += ps.x; s.y += ps.y; s.z += ps.z; s.w += ps.w;
        m.x = fmaxf(m.x, pm.x); m.y = fmaxf(m.y, pm.y);
        m.z = fmaxf(m.z, pm.z); m.w = fmaxf(m.w, pm.w);
    }
    float4 avg;
    avg.x = s.x * (1.0f / CC); avg.y = s.y * (1.0f / CC);
    avg.z = s.z * (1.0f / CC); avg.w = s.w * (1.0f / CC);
    *(float4*)(g_avg + pix) = avg;
    *(float4*)(g_mx + pix)  = m;
}

// ---------------------------------------------------------------------------
// Kernel 2: 7x7 conv + sigmoid on the 2-channel map for one chunk.
// Per-batch spatial op -> safe to run on a batch chunk. All L2-resident.
// ---------------------------------------------------------------------------
__global__ void conv_kernel(const float* __restrict__ cw, int b0) {
    int tid = blockIdx.x * blockDim.x + threadIdx.x;
    if (tid >= CH_NPIX) return;
    int bl = tid / HWSZ;
    int hw = tid - bl * HWSZ;
    int b = b0 + bl;
    int h = hw / WW;
    int w = hw - h * WW;

    const float* base_a = g_avg + (size_t)b * HWSZ;
    const float* base_m = g_mx + (size_t)b * HWSZ;

    float acc = 0.f;
#pragma unroll
    for (int kh = 0; kh < 7; kh++) {
        int ih = h + kh - 3;
        if (ih < 0 || ih >= HH) continue;
#pragma unroll
        for (int kw = 0; kw < 7; kw++) {
            int iw = w + kw - 3;
            if (iw < 0 || iw >= WW) continue;
            int off = ih * WW + iw;
            float wa = __ldg(cw + kh * 7 + kw);        // avg-channel weight
            float wm = __ldg(cw + 49 + kh * 7 + kw);   // max-channel weight
            acc = fmaf(base_a[off], wa, acc);
            acc = fmaf(base_m[off], wm, acc);
        }
    }
    g_att[(size_t)b * HWSZ + hw] = 1.0f / (1.0f + __expf(-acc));
}

// ---------------------------------------------------------------------------
// Kernel 3: out = x * att for one chunk. The chunk of x (51.4 MB) was just
// streamed through L2 by the reduce two launches ago -> reads are L2 hits.
// x read .cs (last use), out stored .cs (never re-read; don't evict chunk2's x).
// ---------------------------------------------------------------------------
__global__ void apply_kernel(const float* __restrict__ x, float* __restrict__ out,
                             int b0) {
    int il = blockIdx.x * blockDim.x + threadIdx.x;  // float4 idx in chunk
    if (il >= CH_NELEM4) return;
    size_t i = (size_t)b0 * CC * HWSZ / 4 + il;      // global float4 idx
    size_t e = i * 4;
    int bc = (int)(e / HWSZ);
    int hw = (int)(e - (size_t)bc * HWSZ);
    int b = bc / CC;

    float4 xv = __ldcs((const float4*)x + i);
    float4 av = *(const float4*)(g_att + (size_t)b * HWSZ + hw);

    float4 o;
    o.x = xv.x * av.x;
    o.y = xv.y * av.y;
    o.z = xv.z * av.z;
    o.w = xv.w * av.w;
    __stcs((float4*)out + i, o);
}

extern "C" void kernel_launch(void* const* d_in, const int* in_sizes, int n_in,
                              void* d_out, int out_size) {
    const float* x  = (const float*)d_in[0];
    const float* cw = (const float*)d_in[1];
    float* out = (float*)d_out;

    for (int c = 0; c < NCHUNK; c++) {
        int b0 = c * BPC;
        {
            dim3 grid((CH_NPIX4 + 255) / 256, G);   // 49 x 8 = 392 blocks
            reduce_partial_kernel<<<grid, 256>>>(x, b0);
        }
        combine_kernel<<<(CH_NPIX4 + 255) / 256, 256>>>(b0);
        conv_kernel<<<(CH_NPIX + 255) / 256, 256>>>(cw, b0);
        apply_kernel<<<(CH_NELEM4 + 255) / 256, 256>>>(x, out, b0);
    }
}